// round 4
// baseline (speedup 1.0000x reference)
#include <cuda_runtime.h>
#include <cstdint>

// Problem constants
#define RR 2048
#define CC 2048
#define DD 64
#define OO 4
#define KP 272            // 256 z-terms + 10 pair + 1 const + 5 zero ; 17 * 16
#define NCHUNK 17         // K chunks of 16

// GEMM tiling
#define BM 128
#define BN 256
#define BK 16
#define NTHREADS 512
#define NSTAGE 4
// per-stage smem: A 128x16 fp32 (8KB) + B 256x16 fp32 (16KB) = 24KB
#define STAGE_FLOATS 6144
#define SMEM_BYTES (NSTAGE * STAGE_FLOATS * 4)   // 98304

// ---------------------------------------------------------------------------
// Scratch in pre-packed tile-image layout (device globals; no allocation).
//   A: [mtile(16)][chunk(17)][128 rows][16 floats]
//   B: [ntile(8) ][chunk(17)][256 rows][16 floats]
// In-row layout (16 floats = 64B): for unit u=0..3 (u = thread tg):
//   [k8=0 pos0, k8=0 pos1, k8=1 pos0, k8=1 pos1]
// where pos0/pos1 are k = k8*8 + u and k8*8 + u + 4.
// One LDS.128 at row*16 + tg*4 yields the fragment pair for BOTH k8 groups.
// 64B rows => 8-row x 16B warp pattern tiles all 32 banks: conflict-free,
// no swizzle needed.
// ---------------------------------------------------------------------------
__device__ float g_A[(size_t)16 * NCHUNK * 2048];
__device__ float g_B[(size_t)8  * NCHUNK * 4096];

__device__ __forceinline__ float tf32r(float x) {
    float y;
    asm("cvt.rna.tf32.f32 %0, %1;" : "=f"(y) : "f"(x));
    return y;
}

__device__ __forceinline__ int rowoff(int k) {
    int kk = k & 15;
    int k8 = kk >> 3, j = kk & 7;
    int u = j & 3, pos = j >> 2;
    return u * 4 + k8 * 2 + pos;
}

__device__ __forceinline__ size_t idxA(int r, int k) {
    int mt = r >> 7, m = r & 127, ck = k >> 4;
    return ((size_t)(mt * NCHUNK + ck) << 11) + m * 16 + rowoff(k);
}

__device__ __forceinline__ size_t idxB(int c, int k) {
    int nt = c >> 8, n = c & 255, ck = k >> 4;
    return ((size_t)(nt * NCHUNK + ck) << 12) + n * 16 + rowoff(k);
}

#define MMA_TF32(c, a0, a1, a2, a3, b0, b1) \
    asm volatile("mma.sync.aligned.m16n8k8.row.col.f32.tf32.tf32.f32 " \
        "{%0,%1,%2,%3}, {%4,%5,%6,%7}, {%8,%9}, {%0,%1,%2,%3};" \
        : "+f"((c)[0]), "+f"((c)[1]), "+f"((c)[2]), "+f"((c)[3]) \
        : "r"(__float_as_uint(a0)), "r"(__float_as_uint(a1)), \
          "r"(__float_as_uint(a2)), "r"(__float_as_uint(a3)), \
          "r"(__float_as_uint(b0)), "r"(__float_as_uint(b1)))

#define CP_ASYNC16(dst_u32, src_ptr) \
    asm volatile("cp.async.cg.shared.global [%0], [%1], 16;" \
                 :: "r"(dst_u32), "l"(src_ptr))

// ---------------------------------------------------------------------------
__global__ void init_out_kernel(float* out) { out[0] = 0.0f; }

// ---------------------------------------------------------------------------
// prep_rows: one warp per row r.
// ---------------------------------------------------------------------------
__global__ void prep_rows_kernel(const float* __restrict__ z_rows) {
    int gw = (blockIdx.x * blockDim.x + threadIdx.x) >> 5;
    int lane = threadIdx.x & 31;
    if (gw >= RR) return;
    int r = gw;

    float z[OO][2];
#pragma unroll
    for (int o = 0; o < OO; o++) {
#pragma unroll
        for (int j = 0; j < 2; j++) {
            int d = lane + j * 32;
            float v = z_rows[((size_t)o * RR + r) * DD + d];
            z[o][j] = v;
            g_A[idxA(r, o * DD + d)] = tf32r(v);
        }
    }
    int p = 0;
#pragma unroll
    for (int o1 = 0; o1 < OO; o1++) {
#pragma unroll
        for (int o2 = o1; o2 < OO; o2++) {
            float part = z[o1][0] * z[o2][0] + z[o1][1] * z[o2][1];
#pragma unroll
            for (int off = 16; off > 0; off >>= 1)
                part += __shfl_xor_sync(0xFFFFFFFFu, part, off);
            if (lane == 0) g_A[idxA(r, 256 + p)] = tf32r(part);
            p++;
        }
    }
    if (lane == 0) g_A[idxA(r, 266)] = 1.0f;
    if (lane < 5) g_A[idxA(r, 267 + lane)] = 0.0f;
}

// ---------------------------------------------------------------------------
// prep_cols: one warp per column c.
// ---------------------------------------------------------------------------
__global__ void prep_cols_kernel(const float* __restrict__ z_cols,
                                 const float* __restrict__ col_times) {
    int gw = (blockIdx.x * blockDim.x + threadIdx.x) >> 5;
    int lane = threadIdx.x & 31;
    if (gw >= CC) return;
    int c = gw;

    float t = col_times[c];
    float coef[OO];
    coef[0] = 1.0f;
    coef[1] = t;
    coef[2] = t * t * 0.5f;
    coef[3] = t * t * t * (1.0f / 6.0f);

    float zc[2];
    float zc2 = 0.0f;
#pragma unroll
    for (int j = 0; j < 2; j++) {
        int d = lane + j * 32;
        zc[j] = z_cols[(size_t)c * DD + d];
        zc2 += zc[j] * zc[j];
    }
#pragma unroll
    for (int off = 16; off > 0; off >>= 1)
        zc2 += __shfl_xor_sync(0xFFFFFFFFu, zc2, off);

#pragma unroll
    for (int o = 0; o < OO; o++) {
#pragma unroll
        for (int j = 0; j < 2; j++) {
            int d = lane + j * 32;
            g_B[idxB(c, o * DD + d)] = tf32r(-2.0f * coef[o] * zc[j]);
        }
    }
    if (lane == 0) {
        int p = 0;
#pragma unroll
        for (int o1 = 0; o1 < OO; o1++) {
#pragma unroll
            for (int o2 = o1; o2 < OO; o2++) {
                float f = (o1 == o2) ? 1.0f : 2.0f;
                g_B[idxB(c, 256 + p)] = tf32r(f * coef[o1] * coef[o2]);
                p++;
            }
        }
        g_B[idxB(c, 266)] = tf32r(zc2);
    }
    if (lane < 5) g_B[idxB(c, 267 + lane)] = 0.0f;
}

// ---------------------------------------------------------------------------
// tf32 mma.sync GEMM + fused epilogue.
// 512 threads, 16 warps: wm = wid>>3 (2 x 64 rows), wn = wid&7 (8 x 32 cols).
// Warp tile 64x32 -> acc 64 regs/thread; 4 warps/SMSP for latency hiding.
// ---------------------------------------------------------------------------
__global__ void __launch_bounds__(NTHREADS, 1)
gemm_mma_kernel(const int* __restrict__ events,
                const float* __restrict__ gamma_rows,
                const float* __restrict__ gamma_cols,
                float* __restrict__ out) {
    extern __shared__ float smem[];
    const uint32_t smem_u = (uint32_t)__cvta_generic_to_shared(smem);

    const int tid  = threadIdx.x;
    const int wid  = tid >> 5;
    const int lane = tid & 31;
    const int wm   = wid >> 3;          // 0..1
    const int wn   = wid & 7;           // 0..7
    const int g    = lane >> 2;         // 0..7
    const int tg   = lane & 3;          // 0..3

    const float* Ag = g_A + ((size_t)(blockIdx.y * NCHUNK) << 11);
    const float* Bg = g_B + ((size_t)(blockIdx.x * NCHUNK) << 12);

    float acc[4][4][4];
#pragma unroll
    for (int mf = 0; mf < 4; mf++)
#pragma unroll
        for (int nf = 0; nf < 4; nf++)
#pragma unroll
            for (int q = 0; q < 4; q++)
                acc[mf][nf][q] = 0.0f;

    // ---- async-copy issue for chunk ck into stage st ----
    auto issue = [&](int ck, int st) {
        uint32_t sa = smem_u + (uint32_t)st * (STAGE_FLOATS * 4);
        const float* aSrc = Ag + ((size_t)ck << 11);
        const float* bSrc = Bg + ((size_t)ck << 12);
        // A: 512 16B lines, 1 per thread
        CP_ASYNC16(sa + tid * 16, aSrc + tid * 4);
        // B: 1024 16B lines, 2 per thread
#pragma unroll
        for (int i = 0; i < 2; i++) {
            int l = tid + i * 512;
            CP_ASYNC16(sa + 8192 + l * 16, bSrc + l * 4);
        }
    };

    auto compute = [&](int st) {
        const float* As = smem + st * STAGE_FLOATS;
        const float* Bs = As + 2048;
        // A fragments: both k8 groups per LDS.128
        float4 alo[4], ahi[4];
#pragma unroll
        for (int mf = 0; mf < 4; mf++) {
            const float* p = As + (wm * 64 + mf * 16 + g) * 16 + tg * 4;
            alo[mf] = *(const float4*)p;
            ahi[mf] = *(const float4*)(p + 128);   // +8 rows
        }
        float4 bv[4];
#pragma unroll
        for (int nf = 0; nf < 4; nf++) {
            const float* p = Bs + (wn * 32 + nf * 8 + g) * 16 + tg * 4;
            bv[nf] = *(const float4*)p;
        }
#pragma unroll
        for (int mf = 0; mf < 4; mf++)
#pragma unroll
            for (int nf = 0; nf < 4; nf++) {
                MMA_TF32(acc[mf][nf], alo[mf].x, ahi[mf].x, alo[mf].y,
                         ahi[mf].y, bv[nf].x, bv[nf].y);
                MMA_TF32(acc[mf][nf], alo[mf].z, ahi[mf].z, alo[mf].w,
                         ahi[mf].w, bv[nf].z, bv[nf].w);
            }
    };

    // ---- pipeline ----
#pragma unroll
    for (int s = 0; s < 3; s++) {
        issue(s, s);
        asm volatile("cp.async.commit_group;");
    }
    for (int ck = 0; ck < NCHUNK; ck++) {
        asm volatile("cp.async.wait_group 2;");
        __syncthreads();
        if (ck + 3 < NCHUNK) issue(ck + 3, (ck + 3) & 3);
        asm volatile("cp.async.commit_group;");   // empty groups keep count
        compute(ck & 3);
        __syncthreads();
    }

    // ---- fused epilogue ----
    const int rbase = blockIdx.y * BM + wm * 64;
    const int cbase = blockIdx.x * BN + wn * 32;

    float lsum = 0.0f;
#pragma unroll
    for (int mf = 0; mf < 4; mf++) {
        const int r0 = rbase + mf * 16 + g;
        const float gr0 = gamma_rows[r0];
        const float gr1 = gamma_rows[r0 + 8];
#pragma unroll
        for (int nf = 0; nf < 4; nf++) {
            const int cc = cbase + nf * 8 + tg * 2;
            const float gc0 = gamma_cols[cc];
            const float gc1 = gamma_cols[cc + 1];
            int2 e0 = *(const int2*)(events + (size_t)r0 * CC + cc);
            int2 e1 = *(const int2*)(events + (size_t)(r0 + 8) * CC + cc);
            const float* d = acc[mf][nf];
            float gr[4] = {gr0, gr0, gr1, gr1};
            float gc[4] = {gc0, gc1, gc0, gc1};
            int   ev[4] = {e0.x, e0.y, e1.x, e1.y};
#pragma unroll
            for (int q = 0; q < 4; q++) {
                float dd = fmaxf(d[q], 0.0f);
                float dist = dd * rsqrtf(fmaxf(dd, 1e-20f));
                float logit = gr[q] + gc[q] - dist;
                float x = ev[q] ? logit : -logit;
                lsum += fminf(x, 0.0f) - __logf(1.0f + __expf(-fabsf(x)));
            }
        }
    }
#pragma unroll
    for (int off = 16; off > 0; off >>= 1)
        lsum += __shfl_xor_sync(0xFFFFFFFFu, lsum, off);
    if (lane == 0) atomicAdd(out, -lsum);
}

// ---------------------------------------------------------------------------
// launch
// ---------------------------------------------------------------------------
extern "C" void kernel_launch(void* const* d_in, const int* in_sizes, int n_in,
                              void* d_out, int out_size) {
    const int*   events     = (const int*)d_in[0];
    const float* col_times  = (const float*)d_in[1];
    const float* z_rows     = (const float*)d_in[2];
    const float* z_cols     = (const float*)d_in[3];
    const float* gamma_rows = (const float*)d_in[4];
    const float* gamma_cols = (const float*)d_in[5];
    float* out = (float*)d_out;

    static int configured = 0;
    if (!configured) {
        cudaFuncSetAttribute(gemm_mma_kernel,
                             cudaFuncAttributeMaxDynamicSharedMemorySize,
                             SMEM_BYTES);
        configured = 1;
    }

    init_out_kernel<<<1, 1>>>(out);
    prep_rows_kernel<<<RR / 8, 256>>>(z_rows);
    prep_cols_kernel<<<CC / 8, 256>>>(z_cols, col_times);

    dim3 grid(CC / BN, RR / BM);   // (8, 16)
    gemm_mma_kernel<<<grid, NTHREADS, SMEM_BYTES>>>(events, gamma_rows,
                                                    gamma_cols, out);
}

// round 5
// speedup vs baseline: 1.1377x; 1.1377x over previous
#include <cuda_runtime.h>
#include <cstdint>

// Problem constants
#define RR 2048
#define CC 2048
#define DD 64
#define OO 4
#define KP 272            // 256 z-terms + 10 pair + 1 const + 5 zero ; 17 * 16
#define NCHUNK 17         // K chunks of 16

// GEMM tiling: 128x128 CTA, 4 warps of 64x64, 2 CTAs/SM
#define BM 128
#define BN 128
#define BK 16
#define NTHREADS 128
#define NSTAGE 4
// per-stage smem: A 128x16 fp32 (8KB) + B 128x16 fp32 (8KB) = 16KB
#define STAGE_FLOATS 4096
#define SMEM_BYTES (NSTAGE * STAGE_FLOATS * 4)   // 65536

// ---------------------------------------------------------------------------
// Scratch in pre-packed tile-image layout (device globals; no allocation).
//   A: [mtile(16)][chunk(17)][128 rows][16 floats]
//   B: [ntile(16)][chunk(17)][128 rows][16 floats]
// In-row layout (16 floats = 64B), unit u = k&3:
//   float index = u*4 + k8*2 + pos   (k8 = (k&15)>>3, pos = (k&7)>>2)
// One LDS.128 at row*16 + tg*4 yields the fragment pair for BOTH k8 groups.
// 64B rows => 8-row x 16B quad pattern tiles all 32 banks: conflict-free.
// ---------------------------------------------------------------------------
__device__ float g_A[(size_t)16 * NCHUNK * 2048];
__device__ float g_B[(size_t)16 * NCHUNK * 2048];

__device__ __forceinline__ float tf32r(float x) {
    float y;
    asm("cvt.rna.tf32.f32 %0, %1;" : "=f"(y) : "f"(x));
    return y;
}

__device__ __forceinline__ int rowoff(int k) {
    int kk = k & 15;
    int k8 = kk >> 3, j = kk & 7;
    int u = j & 3, pos = j >> 2;
    return u * 4 + k8 * 2 + pos;
}

__device__ __forceinline__ size_t idxA(int r, int k) {
    int mt = r >> 7, m = r & 127, ck = k >> 4;
    return ((size_t)(mt * NCHUNK + ck) << 11) + m * 16 + rowoff(k);
}

__device__ __forceinline__ size_t idxB(int c, int k) {
    int nt = c >> 7, n = c & 127, ck = k >> 4;
    return ((size_t)(nt * NCHUNK + ck) << 11) + n * 16 + rowoff(k);
}

#define MMA_TF32(c, a0, a1, a2, a3, b0, b1) \
    asm volatile("mma.sync.aligned.m16n8k8.row.col.f32.tf32.tf32.f32 " \
        "{%0,%1,%2,%3}, {%4,%5,%6,%7}, {%8,%9}, {%0,%1,%2,%3};" \
        : "+f"((c)[0]), "+f"((c)[1]), "+f"((c)[2]), "+f"((c)[3]) \
        : "r"(__float_as_uint(a0)), "r"(__float_as_uint(a1)), \
          "r"(__float_as_uint(a2)), "r"(__float_as_uint(a3)), \
          "r"(__float_as_uint(b0)), "r"(__float_as_uint(b1)))

#define CP_ASYNC16(dst_u32, src_ptr) \
    asm volatile("cp.async.cg.shared.global [%0], [%1], 16;" \
                 :: "r"(dst_u32), "l"(src_ptr))

// ---------------------------------------------------------------------------
__global__ void init_out_kernel(float* out) { out[0] = 0.0f; }

// ---------------------------------------------------------------------------
// prep_rows: one warp per row r.
// ---------------------------------------------------------------------------
__global__ void prep_rows_kernel(const float* __restrict__ z_rows) {
    int gw = (blockIdx.x * blockDim.x + threadIdx.x) >> 5;
    int lane = threadIdx.x & 31;
    if (gw >= RR) return;
    int r = gw;

    float z[OO][2];
#pragma unroll
    for (int o = 0; o < OO; o++) {
#pragma unroll
        for (int j = 0; j < 2; j++) {
            int d = lane + j * 32;
            float v = z_rows[((size_t)o * RR + r) * DD + d];
            z[o][j] = v;
            g_A[idxA(r, o * DD + d)] = tf32r(v);
        }
    }
    int p = 0;
#pragma unroll
    for (int o1 = 0; o1 < OO; o1++) {
#pragma unroll
        for (int o2 = o1; o2 < OO; o2++) {
            float part = z[o1][0] * z[o2][0] + z[o1][1] * z[o2][1];
#pragma unroll
            for (int off = 16; off > 0; off >>= 1)
                part += __shfl_xor_sync(0xFFFFFFFFu, part, off);
            if (lane == 0) g_A[idxA(r, 256 + p)] = tf32r(part);
            p++;
        }
    }
    if (lane == 0) g_A[idxA(r, 266)] = 1.0f;
    if (lane < 5) g_A[idxA(r, 267 + lane)] = 0.0f;
}

// ---------------------------------------------------------------------------
// prep_cols: one warp per column c.
// ---------------------------------------------------------------------------
__global__ void prep_cols_kernel(const float* __restrict__ z_cols,
                                 const float* __restrict__ col_times) {
    int gw = (blockIdx.x * blockDim.x + threadIdx.x) >> 5;
    int lane = threadIdx.x & 31;
    if (gw >= CC) return;
    int c = gw;

    float t = col_times[c];
    float coef[OO];
    coef[0] = 1.0f;
    coef[1] = t;
    coef[2] = t * t * 0.5f;
    coef[3] = t * t * t * (1.0f / 6.0f);

    float zc[2];
    float zc2 = 0.0f;
#pragma unroll
    for (int j = 0; j < 2; j++) {
        int d = lane + j * 32;
        zc[j] = z_cols[(size_t)c * DD + d];
        zc2 += zc[j] * zc[j];
    }
#pragma unroll
    for (int off = 16; off > 0; off >>= 1)
        zc2 += __shfl_xor_sync(0xFFFFFFFFu, zc2, off);

#pragma unroll
    for (int o = 0; o < OO; o++) {
#pragma unroll
        for (int j = 0; j < 2; j++) {
            int d = lane + j * 32;
            g_B[idxB(c, o * DD + d)] = tf32r(-2.0f * coef[o] * zc[j]);
        }
    }
    if (lane == 0) {
        int p = 0;
#pragma unroll
        for (int o1 = 0; o1 < OO; o1++) {
#pragma unroll
            for (int o2 = o1; o2 < OO; o2++) {
                float f = (o1 == o2) ? 1.0f : 2.0f;
                g_B[idxB(c, 256 + p)] = tf32r(f * coef[o1] * coef[o2]);
                p++;
            }
        }
        g_B[idxB(c, 266)] = tf32r(zc2);
    }
    if (lane < 5) g_B[idxB(c, 267 + lane)] = 0.0f;
}

// ---------------------------------------------------------------------------
// tf32 mma.sync GEMM + fused epilogue.
// 128 threads, 4 warps: wm = wid>>1, wn = wid&1; warp tile 64x64.
// 2 CTAs/SM: inter-CTA overlap hides barrier + wait stalls.
// ---------------------------------------------------------------------------
__global__ void __launch_bounds__(NTHREADS, 2)
gemm_mma_kernel(const int* __restrict__ events,
                const float* __restrict__ gamma_rows,
                const float* __restrict__ gamma_cols,
                float* __restrict__ out) {
    extern __shared__ float smem[];
    const uint32_t smem_u = (uint32_t)__cvta_generic_to_shared(smem);

    const int tid  = threadIdx.x;
    const int wid  = tid >> 5;
    const int lane = tid & 31;
    const int wm   = wid >> 1;          // 0..1
    const int wn   = wid & 1;           // 0..1
    const int g    = lane >> 2;         // 0..7
    const int tg   = lane & 3;          // 0..3

    const float* Ag = g_A + ((size_t)(blockIdx.y * NCHUNK) << 11);
    const float* Bg = g_B + ((size_t)(blockIdx.x * NCHUNK) << 11);

    float acc[4][8][4];
#pragma unroll
    for (int mf = 0; mf < 4; mf++)
#pragma unroll
        for (int nf = 0; nf < 8; nf++)
#pragma unroll
            for (int q = 0; q < 4; q++)
                acc[mf][nf][q] = 0.0f;

    // ---- async-copy issue for chunk ck into stage st ----
    auto issue = [&](int ck, int st) {
        uint32_t sa = smem_u + (uint32_t)st * (STAGE_FLOATS * 4);
        const float* aSrc = Ag + ((size_t)ck << 11);
        const float* bSrc = Bg + ((size_t)ck << 11);
#pragma unroll
        for (int i = 0; i < 4; i++) {
            int l = tid + i * 128;
            CP_ASYNC16(sa + l * 16, aSrc + l * 4);
        }
#pragma unroll
        for (int i = 0; i < 4; i++) {
            int l = tid + i * 128;
            CP_ASYNC16(sa + 8192 + l * 16, bSrc + l * 4);
        }
    };

    auto compute = [&](int st) {
        const float* As = smem + st * STAGE_FLOATS;
        const float* Bs = As + 2048;
        float4 alo[4], ahi[4];
#pragma unroll
        for (int mf = 0; mf < 4; mf++) {
            const float* p = As + (wm * 64 + mf * 16 + g) * 16 + tg * 4;
            alo[mf] = *(const float4*)p;
            ahi[mf] = *(const float4*)(p + 128);   // +8 rows
        }
        float4 bv[8];
#pragma unroll
        for (int nf = 0; nf < 8; nf++) {
            const float* p = Bs + (wn * 64 + nf * 8 + g) * 16 + tg * 4;
            bv[nf] = *(const float4*)p;
        }
#pragma unroll
        for (int mf = 0; mf < 4; mf++)
#pragma unroll
            for (int nf = 0; nf < 8; nf++) {
                MMA_TF32(acc[mf][nf], alo[mf].x, ahi[mf].x, alo[mf].y,
                         ahi[mf].y, bv[nf].x, bv[nf].y);
                MMA_TF32(acc[mf][nf], alo[mf].z, ahi[mf].z, alo[mf].w,
                         ahi[mf].w, bv[nf].z, bv[nf].w);
            }
    };

    // ---- pipeline (single barrier per chunk) ----
#pragma unroll
    for (int s = 0; s < 3; s++) {
        issue(s, s);
        asm volatile("cp.async.commit_group;");
    }
    for (int ck = 0; ck < NCHUNK; ck++) {
        asm volatile("cp.async.wait_group 2;");
        __syncthreads();
        if (ck + 3 < NCHUNK) issue(ck + 3, (ck + 3) & 3);
        asm volatile("cp.async.commit_group;");   // empty groups keep count
        compute(ck & 3);
    }

    // ---- fused epilogue ----
    const int rbase = blockIdx.y * BM + wm * 64;
    const int cbase = blockIdx.x * BN + wn * 64;

    float lsum = 0.0f;
#pragma unroll
    for (int mf = 0; mf < 4; mf++) {
        const int r0 = rbase + mf * 16 + g;
        const float gr0 = gamma_rows[r0];
        const float gr1 = gamma_rows[r0 + 8];
#pragma unroll
        for (int nf = 0; nf < 8; nf++) {
            const int cc = cbase + nf * 8 + tg * 2;
            const float gc0 = gamma_cols[cc];
            const float gc1 = gamma_cols[cc + 1];
            int2 e0 = *(const int2*)(events + (size_t)r0 * CC + cc);
            int2 e1 = *(const int2*)(events + (size_t)(r0 + 8) * CC + cc);
            const float* d = acc[mf][nf];
            float gr[4] = {gr0, gr0, gr1, gr1};
            float gc[4] = {gc0, gc1, gc0, gc1};
            int   ev[4] = {e0.x, e0.y, e1.x, e1.y};
#pragma unroll
            for (int q = 0; q < 4; q++) {
                float dd = fmaxf(d[q], 0.0f);
                float dist = dd * rsqrtf(fmaxf(dd, 1e-20f));
                float logit = gr[q] + gc[q] - dist;
                float x = ev[q] ? logit : -logit;
                lsum += fminf(x, 0.0f) - __logf(1.0f + __expf(-fabsf(x)));
            }
        }
    }
#pragma unroll
    for (int off = 16; off > 0; off >>= 1)
        lsum += __shfl_xor_sync(0xFFFFFFFFu, lsum, off);
    if (lane == 0) atomicAdd(out, -lsum);
}

// ---------------------------------------------------------------------------
// launch
// ---------------------------------------------------------------------------
extern "C" void kernel_launch(void* const* d_in, const int* in_sizes, int n_in,
                              void* d_out, int out_size) {
    const int*   events     = (const int*)d_in[0];
    const float* col_times  = (const float*)d_in[1];
    const float* z_rows     = (const float*)d_in[2];
    const float* z_cols     = (const float*)d_in[3];
    const float* gamma_rows = (const float*)d_in[4];
    const float* gamma_cols = (const float*)d_in[5];
    float* out = (float*)d_out;

    static int configured = 0;
    if (!configured) {
        cudaFuncSetAttribute(gemm_mma_kernel,
                             cudaFuncAttributeMaxDynamicSharedMemorySize,
                             SMEM_BYTES);
        configured = 1;
    }

    init_out_kernel<<<1, 1>>>(out);
    prep_rows_kernel<<<RR / 8, 256>>>(z_rows);
    prep_cols_kernel<<<CC / 8, 256>>>(z_cols, col_times);

    dim3 grid(CC / BN, RR / BM);   // (16, 16)
    gemm_mma_kernel<<<grid, NTHREADS, SMEM_BYTES>>>(events, gamma_rows,
                                                    gamma_cols, out);
}

// round 6
// speedup vs baseline: 1.4985x; 1.3171x over previous
#include <cuda_runtime.h>
#include <cuda_bf16.h>
#include <cstdint>

// Problem constants
#define RR 2048
#define CC 2048
#define DD 64
#define OO 4
#define KP 288            // 256 z-terms + 10 pair + 1 const + 21 zero ; 9 * 32
#define NCHUNK 9          // K chunks of 32

// GEMM tiling: 128x128 CTA, 4 warps of 64x64, 2 CTAs/SM
#define BM 128
#define BN 128
#define NTHREADS 128
#define NSTAGE 4
// per-stage smem: A 128x32 bf16 (8KB) + B 128x32 bf16 (8KB) = 16KB
#define STAGE_ELEMS 8192
#define SMEM_BYTES (NSTAGE * STAGE_ELEMS * 2)    // 65536

// ---------------------------------------------------------------------------
// Scratch in pre-packed bf16 tile-image layout.
//   A: [mtile(16)][chunk(9)][128 rows][32 bf16]   (row = 64 B)
//   B: [ntile(16)][chunk(9)][128 rows][32 bf16]
// Row packing for m16n8k16 fragments: k in chunk (kk=k&31):
//   grp = kk>>4 (which k16 group), j = kk&15, pr = j>>1, w = j&1
//   unit = ((pr&3)<<2) | (grp<<1) | (pr>>2) ;  bf16 off = unit*2 + w
// Thread tg's 16B at row*64 + tg*16 then holds, in order:
//   [k16a a0-pair][k16a a2-pair][k16b a0-pair][k16b a2-pair]
// Warp access row*64+tg*16 is contiguous 128B per LDS.128 phase: conflict-free.
// ---------------------------------------------------------------------------
__device__ __nv_bfloat16 g_A[(size_t)16 * NCHUNK * 4096];
__device__ __nv_bfloat16 g_B[(size_t)16 * NCHUNK * 4096];

__device__ __forceinline__ int rowoff16(int k) {
    int kk = k & 31;
    int grp = kk >> 4, j = kk & 15;
    int pr = j >> 1, w = j & 1;
    int unit = ((pr & 3) << 2) | (grp << 1) | (pr >> 2);
    return unit * 2 + w;
}

__device__ __forceinline__ size_t idxA(int r, int k) {
    int mt = r >> 7, m = r & 127, ck = k >> 5;
    return ((size_t)(mt * NCHUNK + ck) << 12) + m * 32 + rowoff16(k);
}

__device__ __forceinline__ size_t idxB(int c, int k) {
    int nt = c >> 7, n = c & 127, ck = k >> 5;
    return ((size_t)(nt * NCHUNK + ck) << 12) + n * 32 + rowoff16(k);
}

#define MMA_BF16(c, a0, a1, a2, a3, b0, b1) \
    asm volatile("mma.sync.aligned.m16n8k16.row.col.f32.bf16.bf16.f32 " \
        "{%0,%1,%2,%3}, {%4,%5,%6,%7}, {%8,%9}, {%0,%1,%2,%3};" \
        : "+f"((c)[0]), "+f"((c)[1]), "+f"((c)[2]), "+f"((c)[3]) \
        : "r"(a0), "r"(a1), "r"(a2), "r"(a3), "r"(b0), "r"(b1))

#define CP_ASYNC16(dst_u32, src_ptr) \
    asm volatile("cp.async.cg.shared.global [%0], [%1], 16;" \
                 :: "r"(dst_u32), "l"(src_ptr))

// ---------------------------------------------------------------------------
__global__ void init_out_kernel(float* out) { out[0] = 0.0f; }

// ---------------------------------------------------------------------------
// prep_rows: one warp per row r.
// ---------------------------------------------------------------------------
__global__ void prep_rows_kernel(const float* __restrict__ z_rows) {
    int gw = (blockIdx.x * blockDim.x + threadIdx.x) >> 5;
    int lane = threadIdx.x & 31;
    if (gw >= RR) return;
    int r = gw;

    float z[OO][2];
#pragma unroll
    for (int o = 0; o < OO; o++) {
#pragma unroll
        for (int j = 0; j < 2; j++) {
            int d = lane + j * 32;
            float v = z_rows[((size_t)o * RR + r) * DD + d];
            z[o][j] = v;
            g_A[idxA(r, o * DD + d)] = __float2bfloat16_rn(v);
        }
    }
    int p = 0;
#pragma unroll
    for (int o1 = 0; o1 < OO; o1++) {
#pragma unroll
        for (int o2 = o1; o2 < OO; o2++) {
            float part = z[o1][0] * z[o2][0] + z[o1][1] * z[o2][1];
#pragma unroll
            for (int off = 16; off > 0; off >>= 1)
                part += __shfl_xor_sync(0xFFFFFFFFu, part, off);
            if (lane == 0) g_A[idxA(r, 256 + p)] = __float2bfloat16_rn(part);
            p++;
        }
    }
    if (lane == 0) g_A[idxA(r, 266)] = __float2bfloat16_rn(1.0f);
    if (lane < 21) g_A[idxA(r, 267 + lane)] = __float2bfloat16_rn(0.0f);
}

// ---------------------------------------------------------------------------
// prep_cols: one warp per column c.
// ---------------------------------------------------------------------------
__global__ void prep_cols_kernel(const float* __restrict__ z_cols,
                                 const float* __restrict__ col_times) {
    int gw = (blockIdx.x * blockDim.x + threadIdx.x) >> 5;
    int lane = threadIdx.x & 31;
    if (gw >= CC) return;
    int c = gw;

    float t = col_times[c];
    float coef[OO];
    coef[0] = 1.0f;
    coef[1] = t;
    coef[2] = t * t * 0.5f;
    coef[3] = t * t * t * (1.0f / 6.0f);

    float zc[2];
    float zc2 = 0.0f;
#pragma unroll
    for (int j = 0; j < 2; j++) {
        int d = lane + j * 32;
        zc[j] = z_cols[(size_t)c * DD + d];
        zc2 += zc[j] * zc[j];
    }
#pragma unroll
    for (int off = 16; off > 0; off >>= 1)
        zc2 += __shfl_xor_sync(0xFFFFFFFFu, zc2, off);

#pragma unroll
    for (int o = 0; o < OO; o++) {
#pragma unroll
        for (int j = 0; j < 2; j++) {
            int d = lane + j * 32;
            g_B[idxB(c, o * DD + d)] = __float2bfloat16_rn(-2.0f * coef[o] * zc[j]);
        }
    }
    if (lane == 0) {
        int p = 0;
#pragma unroll
        for (int o1 = 0; o1 < OO; o1++) {
#pragma unroll
            for (int o2 = o1; o2 < OO; o2++) {
                float f = (o1 == o2) ? 1.0f : 2.0f;
                g_B[idxB(c, 256 + p)] = __float2bfloat16_rn(f * coef[o1] * coef[o2]);
                p++;
            }
        }
        g_B[idxB(c, 266)] = __float2bfloat16_rn(zc2);
    }
    if (lane < 21) g_B[idxB(c, 267 + lane)] = __float2bfloat16_rn(0.0f);
}

// ---------------------------------------------------------------------------
// bf16 mma.sync GEMM + fused epilogue.
// 128 threads, 4 warps: warp tile 64x64; 2 CTAs/SM.
// ---------------------------------------------------------------------------
__global__ void __launch_bounds__(NTHREADS, 2)
gemm_mma_kernel(const int* __restrict__ events,
                const float* __restrict__ gamma_rows,
                const float* __restrict__ gamma_cols,
                float* __restrict__ out) {
    extern __shared__ __nv_bfloat16 smem[];
    const uint32_t smem_u = (uint32_t)__cvta_generic_to_shared(smem);

    const int tid  = threadIdx.x;
    const int wid  = tid >> 5;
    const int lane = tid & 31;
    const int wm   = wid >> 1;          // 0..1
    const int wn   = wid & 1;           // 0..1
    const int g    = lane >> 2;         // 0..7
    const int tg   = lane & 3;          // 0..3

    const __nv_bfloat16* Ag = g_A + ((size_t)(blockIdx.y * NCHUNK) << 12);
    const __nv_bfloat16* Bg = g_B + ((size_t)(blockIdx.x * NCHUNK) << 12);

    float acc[4][8][4];
#pragma unroll
    for (int mf = 0; mf < 4; mf++)
#pragma unroll
        for (int nf = 0; nf < 8; nf++)
#pragma unroll
            for (int q = 0; q < 4; q++)
                acc[mf][nf][q] = 0.0f;

    // ---- async-copy issue for chunk ck into stage st (16 KB) ----
    auto issue = [&](int ck, int st) {
        uint32_t sa = smem_u + (uint32_t)st * (STAGE_ELEMS * 2);
        const __nv_bfloat16* aSrc = Ag + ((size_t)ck << 12);
        const __nv_bfloat16* bSrc = Bg + ((size_t)ck << 12);
#pragma unroll
        for (int i = 0; i < 4; i++) {
            int l = tid + i * 128;
            CP_ASYNC16(sa + l * 16, aSrc + l * 8);
        }
#pragma unroll
        for (int i = 0; i < 4; i++) {
            int l = tid + i * 128;
            CP_ASYNC16(sa + 8192 + l * 16, bSrc + l * 8);
        }
    };

    auto compute = [&](int st) {
        const __nv_bfloat16* As = smem + st * STAGE_ELEMS;
        const __nv_bfloat16* Bs = As + 4096;
        uint4 alo[4], ahi[4];
#pragma unroll
        for (int mf = 0; mf < 4; mf++) {
            const __nv_bfloat16* p = As + (wm * 64 + mf * 16 + g) * 32 + tg * 8;
            alo[mf] = *(const uint4*)p;
            ahi[mf] = *(const uint4*)(p + 256);   // +8 rows
        }
        uint4 bv[8];
#pragma unroll
        for (int nf = 0; nf < 8; nf++) {
            const __nv_bfloat16* p = Bs + (wn * 64 + nf * 8 + g) * 32 + tg * 8;
            bv[nf] = *(const uint4*)p;
        }
#pragma unroll
        for (int mf = 0; mf < 4; mf++)
#pragma unroll
            for (int nf = 0; nf < 8; nf++) {
                MMA_BF16(acc[mf][nf], alo[mf].x, ahi[mf].x, alo[mf].y,
                         ahi[mf].y, bv[nf].x, bv[nf].y);
                MMA_BF16(acc[mf][nf], alo[mf].z, ahi[mf].z, alo[mf].w,
                         ahi[mf].w, bv[nf].z, bv[nf].w);
            }
    };

    // ---- pipeline (single barrier per chunk) ----
#pragma unroll
    for (int s = 0; s < 3; s++) {
        issue(s, s);
        asm volatile("cp.async.commit_group;");
    }
    for (int ck = 0; ck < NCHUNK; ck++) {
        asm volatile("cp.async.wait_group 2;");
        __syncthreads();
        if (ck + 3 < NCHUNK) issue(ck + 3, (ck + 3) & 3);
        asm volatile("cp.async.commit_group;");   // empty groups keep count
        compute(ck & 3);
    }

    // ---- fused epilogue ----
    const int rbase = blockIdx.y * BM + wm * 64;
    const int cbase = blockIdx.x * BN + wn * 64;

    float lsum = 0.0f;
#pragma unroll
    for (int mf = 0; mf < 4; mf++) {
        const int r0 = rbase + mf * 16 + g;
        const float gr0 = gamma_rows[r0];
        const float gr1 = gamma_rows[r0 + 8];
#pragma unroll
        for (int nf = 0; nf < 8; nf++) {
            const int cc = cbase + nf * 8 + tg * 2;
            const float gc0 = gamma_cols[cc];
            const float gc1 = gamma_cols[cc + 1];
            int2 e0 = *(const int2*)(events + (size_t)r0 * CC + cc);
            int2 e1 = *(const int2*)(events + (size_t)(r0 + 8) * CC + cc);
            const float* d = acc[mf][nf];
            float gr[4] = {gr0, gr0, gr1, gr1};
            float gc[4] = {gc0, gc1, gc0, gc1};
            int   ev[4] = {e0.x, e0.y, e1.x, e1.y};
#pragma unroll
            for (int q = 0; q < 4; q++) {
                float dd = fmaxf(d[q], 0.0f);
                float dist = dd * rsqrtf(fmaxf(dd, 1e-20f));
                float logit = gr[q] + gc[q] - dist;
                float x = ev[q] ? logit : -logit;
                lsum += fminf(x, 0.0f) - __logf(1.0f + __expf(-fabsf(x)));
            }
        }
    }
#pragma unroll
    for (int off = 16; off > 0; off >>= 1)
        lsum += __shfl_xor_sync(0xFFFFFFFFu, lsum, off);
    if (lane == 0) atomicAdd(out, -lsum);
}

// ---------------------------------------------------------------------------
// launch
// ---------------------------------------------------------------------------
extern "C" void kernel_launch(void* const* d_in, const int* in_sizes, int n_in,
                              void* d_out, int out_size) {
    const int*   events     = (const int*)d_in[0];
    const float* col_times  = (const float*)d_in[1];
    const float* z_rows     = (const float*)d_in[2];
    const float* z_cols     = (const float*)d_in[3];
    const float* gamma_rows = (const float*)d_in[4];
    const float* gamma_cols = (const float*)d_in[5];
    float* out = (float*)d_out;

    static int configured = 0;
    if (!configured) {
        cudaFuncSetAttribute(gemm_mma_kernel,
                             cudaFuncAttributeMaxDynamicSharedMemorySize,
                             SMEM_BYTES);
        configured = 1;
    }

    init_out_kernel<<<1, 1>>>(out);
    prep_rows_kernel<<<RR / 8, 256>>>(z_rows);
    prep_cols_kernel<<<CC / 8, 256>>>(z_cols, col_times);

    dim3 grid(CC / BN, RR / BM);   // (16, 16)
    gemm_mma_kernel<<<grid, NTHREADS, SMEM_BYTES>>>(events, gamma_rows,
                                                    gamma_cols, out);
}